// round 13
// baseline (speedup 1.0000x reference)
#include <cuda_runtime.h>
#include <math.h>
#include <stdint.h>

// PPCA gating layer, GB300 sm_103a — round 13: R10 with 12/4 staging split.
// x: [B=64, C=256, H=56, W=56] fp32, weight: [HW=3136, 15] fp32.
//
// R11/R12 (phase restructuring) both lost to R10's plain structure; reverted.
// Single dial left per the cross-round model: L1D carveout after smem
// (R4: 226KB->77.5%, R10: 80KB->75.5%, R8: 3KB->55%). Shift staging from
// 8 reg / 8 smem to 12 reg / 4 smem: smem/CTA 37->20.3KB, carveout 80->147KB,
// everything else (256 thr, depth 16, 4 CTAs, cp.async for the smem half)
// identical to R10. Reg budget ~62 under the 64 cap.

#define BATCH   64
#define CH      256
#define HW      3136
#define HW4     (HW / 4)      // 784 float4 per (b,c) row
#define TILE_S  64
#define LANES   (TILE_S / 4)  // 16 float4 lanes
#define NTHR    256           // 16 lanes x 16 half-groups
#define NREG    12            // channels summed via LDG into registers
#define NSMEM   4             // channels staged via cp.async.cg into smem

#define CP_ASYNC_CG16(dst_u32, src_ptr) \
    asm volatile("cp.async.cg.shared.global [%0], [%1], 16;" \
                 :: "r"(dst_u32), "l"(src_ptr) : "memory")
#define CP_ASYNC_WAIT_ALL() \
    asm volatile("cp.async.wait_all;" ::: "memory")

__global__ __launch_bounds__(NTHR, 4)
void ppca_gate_kernel(const float* __restrict__ x,
                      const float* __restrict__ weight,
                      float* __restrict__ out)
{
    __shared__ float4 sstage[NSMEM * NTHR];   // 16 KB staging (cp.async dst)
    __shared__ float  sgrp[16 * TILE_S];      // half-group sums [16][64]
    __shared__ float  sgate[TILE_S];          // gates

    const int s0 = blockIdx.x * TILE_S;       // 49 tiles * 64 = 3136
    const int b  = blockIdx.y;

    const int t   = threadIdx.x;
    const int sl4 = t & (LANES - 1);          // float4 lane 0..15
    const int h   = t >> 4;                   // half-group 0..15 (16 ch each)

    const size_t base4 = (size_t)b * CH * HW4 + (size_t)(blockIdx.x * LANES) + sl4
                       + (size_t)(h * 16) * HW4;
    const float4* xb4 = reinterpret_cast<const float4*>(x) + base4;

    // ---- Pass 1a: queue 4 cp.async.cg 16B copies (bypass L1/RF) ----
    const uint32_t sbase =
        (uint32_t)__cvta_generic_to_shared(&sstage[t]);
    #pragma unroll
    for (int cc = 0; cc < NSMEM; cc++) {
        CP_ASYNC_CG16(sbase + cc * NTHR * 16,
                      xb4 + (size_t)(NREG + cc) * HW4);
    }

    // ---- Pass 1b: 12 LDG.128 sums while copies are in flight ----
    float4 r[NREG];
    float s0a = 0.f, s1a = 0.f, s2a = 0.f, s3a = 0.f;
    #pragma unroll
    for (int cc = 0; cc < NREG; cc++) {
        r[cc] = __ldg(xb4 + (size_t)cc * HW4);
        s0a += r[cc].x; s1a += r[cc].y; s2a += r[cc].z; s3a += r[cc].w;
    }

    // ---- Pass 1c: drain this thread's copies, finish sums from smem ----
    CP_ASYNC_WAIT_ALL();
    #pragma unroll
    for (int cc = 0; cc < NSMEM; cc++) {
        float4 v = sstage[cc * NTHR + t];
        s0a += v.x; s1a += v.y; s2a += v.z; s3a += v.w;
    }
    reinterpret_cast<float4*>(sgrp)[h * LANES + sl4] =
        make_float4(s0a, s1a, s2a, s3a);
    __syncthreads();

    // ---- Gate computation: one thread per spatial location ----
    if (t < TILE_S) {
        float S8[8];
        #pragma unroll
        for (int j = 0; j < 8; j++)
            S8[j] = sgrp[(2*j) * TILE_S + t] + sgrp[(2*j+1) * TILE_S + t];

        float S4[4], S2[2], S1;
        #pragma unroll
        for (int j = 0; j < 4; j++) S4[j] = S8[2*j] + S8[2*j+1];
        S2[0] = S4[0] + S4[1];
        S2[1] = S4[2] + S4[3];
        S1    = S2[0] + S2[1];

        // feats in reference concat order: [scale1, scale2, scale4, scale8]
        float f[15];
        f[0] = S1 * (1.0f / 256.0f);
        f[1] = S2[0] * (1.0f / 128.0f);
        f[2] = S2[1] * (1.0f / 128.0f);
        #pragma unroll
        for (int j = 0; j < 4; j++) f[3 + j] = S4[j] * (1.0f / 64.0f);
        #pragma unroll
        for (int j = 0; j < 8; j++) f[7 + j] = S8[j] * (1.0f / 32.0f);

        float mu = 0.0f;
        #pragma unroll
        for (int j = 0; j < 15; j++) mu += f[j];
        mu *= (1.0f / 15.0f);

        float var = 0.0f;
        #pragma unroll
        for (int j = 0; j < 15; j++) {
            float d = f[j] - mu;
            var += d * d;
        }
        var *= (1.0f / 15.0f);
        const float inv_std = rsqrtf(var);

        const float* wr = weight + (size_t)(s0 + t) * 15;
        float z = 0.0f;
        #pragma unroll
        for (int j = 0; j < 15; j++)
            z += (f[j] - mu) * __ldg(wr + j);
        z *= inv_std;

        sgate[t] = 1.0f / (1.0f + expf(-z));
    }
    __syncthreads();

    // ---- Pass 2: multiply staged data by gate, default (.wb) stores ----
    const float4 gate4 = reinterpret_cast<const float4*>(sgate)[sl4];
    float4* ob4 = reinterpret_cast<float4*>(out) + base4;

    #pragma unroll
    for (int cc = 0; cc < NREG; cc++) {
        float4 v = r[cc];
        v.x *= gate4.x; v.y *= gate4.y; v.z *= gate4.z; v.w *= gate4.w;
        ob4[(size_t)cc * HW4] = v;
    }
    #pragma unroll
    for (int cc = 0; cc < NSMEM; cc++) {
        float4 v = sstage[cc * NTHR + t];
        v.x *= gate4.x; v.y *= gate4.y; v.z *= gate4.z; v.w *= gate4.w;
        ob4[(size_t)(NREG + cc) * HW4] = v;
    }
}

extern "C" void kernel_launch(void* const* d_in, const int* in_sizes, int n_in,
                              void* d_out, int out_size)
{
    const float* x      = (const float*)d_in[0];
    const float* weight = (const float*)d_in[1];
    float* out          = (float*)d_out;

    dim3 grid(HW / TILE_S, BATCH);   // (49, 64)
    ppca_gate_kernel<<<grid, NTHR>>>(x, weight, out);
}

// round 14
// speedup vs baseline: 1.0317x; 1.0317x over previous
#include <cuda_runtime.h>
#include <math.h>
#include <stdint.h>

// PPCA gating layer, GB300 sm_103a — round 14 (final shape): R10 with the
// LDG block issued BEFORE the cp.async block.
// x: [B=64, C=256, H=56, W=56] fp32, weight: [HW=3136, 15] fp32.
//
// Convergence evidence: R11 (barrier-free epilogue), R12 (2-tile pipeline),
// R13 (12/4 split, more L1 carveout) all regressed from R10. R10's shape —
// 256 thr = 16 float4-lanes x 16 half-groups, depth 16 (8 LDG reg + 8
// cp.async smem), 4 CTAs/SM, default cache policy — is the empirical
// optimum (ncu 59.1us, DRAM 75.5%, traffic at the 353MB floor).
//
// Micro-fix here: LDGSTS costs ~8 LSU cyc/op vs ~2 for LDG; issuing the
// 8 cp.async first delayed the latency-critical register loads (which gate
// the pre-barrier accumulation) by ~60 cycles. Issue LDG first; cp.async
// results are only needed at wait_all, behind 8 load latencies regardless.

#define BATCH   64
#define CH      256
#define HW      3136
#define HW4     (HW / 4)      // 784 float4 per (b,c) row
#define TILE_S  64
#define LANES   (TILE_S / 4)  // 16 float4 lanes
#define NTHR    256           // 16 lanes x 16 half-groups
#define NREG    8             // channels summed via LDG into registers
#define NSMEM   8             // channels staged via cp.async.cg into smem

#define CP_ASYNC_CG16(dst_u32, src_ptr) \
    asm volatile("cp.async.cg.shared.global [%0], [%1], 16;" \
                 :: "r"(dst_u32), "l"(src_ptr) : "memory")
#define CP_ASYNC_WAIT_ALL() \
    asm volatile("cp.async.wait_all;" ::: "memory")

__global__ __launch_bounds__(NTHR, 4)
void ppca_gate_kernel(const float* __restrict__ x,
                      const float* __restrict__ weight,
                      float* __restrict__ out)
{
    __shared__ float4 sstage[NSMEM * NTHR];   // 32 KB staging (cp.async dst)
    __shared__ float  sgrp[16 * TILE_S];      // half-group sums [16][64]
    __shared__ float  sgate[TILE_S];          // gates

    const int s0 = blockIdx.x * TILE_S;       // 49 tiles * 64 = 3136
    const int b  = blockIdx.y;

    const int t   = threadIdx.x;
    const int sl4 = t & (LANES - 1);          // float4 lane 0..15
    const int h   = t >> 4;                   // half-group 0..15 (16 ch each)

    const size_t base4 = (size_t)b * CH * HW4 + (size_t)(blockIdx.x * LANES) + sl4
                       + (size_t)(h * 16) * HW4;
    const float4* xb4 = reinterpret_cast<const float4*>(x) + base4;

    // ---- Pass 1a: 8 LDG.128 into registers FIRST (critical path) ----
    float4 r[NREG];
    #pragma unroll
    for (int cc = 0; cc < NREG; cc++)
        r[cc] = __ldg(xb4 + (size_t)cc * HW4);

    // ---- Pass 1b: queue 8 cp.async.cg 16B copies (bypass L1/RF) ----
    const uint32_t sbase =
        (uint32_t)__cvta_generic_to_shared(&sstage[t]);
    #pragma unroll
    for (int cc = 0; cc < NSMEM; cc++) {
        CP_ASYNC_CG16(sbase + cc * NTHR * 16,
                      xb4 + (size_t)(NREG + cc) * HW4);
    }

    // ---- accumulate register half while copies are in flight ----
    float s0a = 0.f, s1a = 0.f, s2a = 0.f, s3a = 0.f;
    #pragma unroll
    for (int cc = 0; cc < NREG; cc++) {
        s0a += r[cc].x; s1a += r[cc].y; s2a += r[cc].z; s3a += r[cc].w;
    }

    // ---- Pass 1c: drain this thread's copies, finish sums from smem ----
    CP_ASYNC_WAIT_ALL();
    #pragma unroll
    for (int cc = 0; cc < NSMEM; cc++) {
        float4 v = sstage[cc * NTHR + t];
        s0a += v.x; s1a += v.y; s2a += v.z; s3a += v.w;
    }
    reinterpret_cast<float4*>(sgrp)[h * LANES + sl4] =
        make_float4(s0a, s1a, s2a, s3a);
    __syncthreads();

    // ---- Gate computation: one thread per spatial location ----
    if (t < TILE_S) {
        float S8[8];
        #pragma unroll
        for (int j = 0; j < 8; j++)
            S8[j] = sgrp[(2*j) * TILE_S + t] + sgrp[(2*j+1) * TILE_S + t];

        float S4[4], S2[2], S1;
        #pragma unroll
        for (int j = 0; j < 4; j++) S4[j] = S8[2*j] + S8[2*j+1];
        S2[0] = S4[0] + S4[1];
        S2[1] = S4[2] + S4[3];
        S1    = S2[0] + S2[1];

        // feats in reference concat order: [scale1, scale2, scale4, scale8]
        float f[15];
        f[0] = S1 * (1.0f / 256.0f);
        f[1] = S2[0] * (1.0f / 128.0f);
        f[2] = S2[1] * (1.0f / 128.0f);
        #pragma unroll
        for (int j = 0; j < 4; j++) f[3 + j] = S4[j] * (1.0f / 64.0f);
        #pragma unroll
        for (int j = 0; j < 8; j++) f[7 + j] = S8[j] * (1.0f / 32.0f);

        float mu = 0.0f;
        #pragma unroll
        for (int j = 0; j < 15; j++) mu += f[j];
        mu *= (1.0f / 15.0f);

        float var = 0.0f;
        #pragma unroll
        for (int j = 0; j < 15; j++) {
            float d = f[j] - mu;
            var += d * d;
        }
        var *= (1.0f / 15.0f);
        const float inv_std = rsqrtf(var);

        const float* wr = weight + (size_t)(s0 + t) * 15;
        float z = 0.0f;
        #pragma unroll
        for (int j = 0; j < 15; j++)
            z += (f[j] - mu) * __ldg(wr + j);
        z *= inv_std;

        sgate[t] = 1.0f / (1.0f + expf(-z));
    }
    __syncthreads();

    // ---- Pass 2: multiply staged data by gate, default (.wb) stores ----
    const float4 gate4 = reinterpret_cast<const float4*>(sgate)[sl4];
    float4* ob4 = reinterpret_cast<float4*>(out) + base4;

    #pragma unroll
    for (int cc = 0; cc < NREG; cc++) {
        float4 v = r[cc];
        v.x *= gate4.x; v.y *= gate4.y; v.z *= gate4.z; v.w *= gate4.w;
        ob4[(size_t)cc * HW4] = v;
    }
    #pragma unroll
    for (int cc = 0; cc < NSMEM; cc++) {
        float4 v = sstage[cc * NTHR + t];
        v.x *= gate4.x; v.y *= gate4.y; v.z *= gate4.z; v.w *= gate4.w;
        ob4[(size_t)(NREG + cc) * HW4] = v;
    }
}

extern "C" void kernel_launch(void* const* d_in, const int* in_sizes, int n_in,
                              void* d_out, int out_size)
{
    const float* x      = (const float*)d_in[0];
    const float* weight = (const float*)d_in[1];
    float* out          = (float*)d_out;

    dim3 grid(HW / TILE_S, BATCH);   // (49, 64)
    ppca_gate_kernel<<<grid, NTHR>>>(x, weight, out);
}